// round 1
// baseline (speedup 1.0000x reference)
#include <cuda_runtime.h>
#include <math.h>

#define NB 16
#define CH 512
#define HW 1024

// ---------------- scratch (static device globals; no runtime allocation) ----
__device__ float g_ghat[32*32];            // separable gaussian factor ghat[i][y]
__device__ float g_s[NB*CH];               // per-(b,c) spatial mean
__device__ float g_ysc[NB*CH];             // SE scale
__device__ float g_fT[(size_t)NB*HW*CH];   // out32 transposed: [b][p][c]
__device__ float g_sigT[(size_t)NB*HW*CH]; // sigmoid(out32): [b][p][c]
__device__ float g_w1buf[(size_t)NB*32*32*CH]; // stage-A intermediate [b][y][k][c]
__device__ float g_act[(size_t)NB*1024*1024];  // cat in viewed layout [b][i][p']
__device__ float g_z[(size_t)NB*CH*HW];        // pre-norm GEMM output

// ---------------- ghat extraction: ghat[i][y] = sum_x gus[(i*32+0), y, x] ----
__global__ void k_ghat(const float* __restrict__ gus) {
    int t = threadIdx.x;              // 1024 threads
    int i = t >> 5, y = t & 31;
    const float* p = gus + (size_t)(i*32)*1024 + y*32;
    float s = 0.f;
    #pragma unroll
    for (int x = 0; x < 32; x++) s += p[x];
    g_ghat[t] = s;
}

// ---------------- SE: spatial mean --------------------------------------
__global__ void k_se_reduce(const float* __restrict__ x) {
    int c = blockIdx.x, b = blockIdx.y, t = threadIdx.x; // 128 threads
    const float* p = x + ((size_t)(b*CH + c))*HW;
    float s = 0.f;
    #pragma unroll
    for (int j = 0; j < 8; j++) s += p[t + j*128];
    #pragma unroll
    for (int o = 16; o; o >>= 1) s += __shfl_xor_sync(~0u, s, o);
    __shared__ float ws[4];
    if ((t & 31) == 0) ws[t >> 5] = s;
    __syncthreads();
    if (t == 0) g_s[b*CH + c] = (ws[0]+ws[1]+ws[2]+ws[3]) * (1.0f/HW);
}

// ---------------- SE: tiny MLP -------------------------------------------
__global__ void k_se_mlp(const float* __restrict__ w1, const float* __restrict__ b1,
                         const float* __restrict__ w2, const float* __restrict__ b2) {
    int b = blockIdx.x, t = threadIdx.x; // 512 threads
    __shared__ float ssh[CH];
    __shared__ float hsh[32];
    ssh[t] = g_s[b*CH + t];
    __syncthreads();
    if (t < 32) {
        float a = b1[t];
        const float* w = w1 + t*CH;
        for (int c = 0; c < CH; c++) a += w[c]*ssh[c];
        hsh[t] = fmaxf(a, 0.f);
    }
    __syncthreads();
    float a = b2[t];
    const float* w = w2 + t*32;
    #pragma unroll
    for (int j = 0; j < 32; j++) a += w[j]*hsh[j];
    g_ysc[b*CH + t] = 1.f/(1.f + __expf(-a));
}

// ---------------- out32 transpose -> [b][p][c] + sigmoid -----------------
__global__ void k_makeT(const float* __restrict__ x) {
    int p0 = blockIdx.x*32, c0 = blockIdx.y*32, b = blockIdx.z;
    int tx = threadIdx.x, ty = threadIdx.y;   // (32, 8)
    __shared__ float tile[32][33];
    #pragma unroll
    for (int i = 0; i < 4; i++) {
        int c = c0 + ty + i*8;
        tile[ty+i*8][tx] = x[((size_t)(b*CH + c))*HW + p0 + tx] * g_ysc[b*CH + c];
    }
    __syncthreads();
    #pragma unroll
    for (int i = 0; i < 4; i++) {
        int p = p0 + ty + i*8;
        float v = tile[tx][ty+i*8];
        size_t idx = ((size_t)(b*HW + p))*CH + c0 + tx;
        g_fT[idx] = v;
        g_sigT[idx] = 1.f/(1.f + __expf(-v));
    }
}

// ---------------- gus stage A: W1[b,y,k,c] = sum_x ghat[k,x]*fT[b,y*32+x,c]
__global__ void k_gusA() {
    int y = blockIdx.x, b = blockIdx.y, t = threadIdx.x; // 256
    __shared__ float ghT[1024];        // ghT[x*32+k] = ghat[k][x]
    __shared__ float slab[32][256];
    for (int idx = t; idx < 1024; idx += 256) {
        int xx = idx >> 5, k = idx & 31;
        ghT[idx] = g_ghat[k*32 + xx];
    }
    for (int cc = 0; cc < CH; cc += 256) {
        __syncthreads();
        for (int idx = t; idx < 32*256; idx += 256) {
            int xr = idx >> 8, c = idx & 255;
            slab[xr][c] = g_fT[((size_t)(b*HW + y*32 + xr))*CH + cc + c];
        }
        __syncthreads();
        float acc[32];
        #pragma unroll
        for (int k = 0; k < 32; k++) acc[k] = 0.f;
        #pragma unroll
        for (int xx = 0; xx < 32; xx++) {
            float v = slab[xx][t];
            const float4* gp = (const float4*)&ghT[xx*32];
            #pragma unroll
            for (int q = 0; q < 8; q++) {
                float4 g4 = gp[q];
                acc[q*4+0] += g4.x*v; acc[q*4+1] += g4.y*v;
                acc[q*4+2] += g4.z*v; acc[q*4+3] += g4.w*v;
            }
        }
        #pragma unroll
        for (int k = 0; k < 32; k++)
            g_w1buf[((size_t)((b*32 + y)*32 + k))*CH + cc + t] = acc[k];
    }
}

// ---------------- gus stage B -> write directly into viewed layout -------
__global__ void k_gusB() {
    int k = blockIdx.x, b = blockIdx.y, t = threadIdx.x; // 256
    __shared__ float ghB[1024];        // ghB[y*32+i] = ghat[i][y]
    __shared__ float slab[32][256];
    for (int idx = t; idx < 1024; idx += 256) {
        int yy = idx >> 5, i = idx & 31;
        ghB[idx] = g_ghat[i*32 + yy];
    }
    int half = k & 1, kr = k >> 1;
    for (int cc = 0; cc < CH; cc += 256) {
        __syncthreads();
        for (int idx = t; idx < 32*256; idx += 256) {
            int yr = idx >> 8, c = idx & 255;
            slab[yr][c] = g_w1buf[((size_t)((b*32 + yr)*32 + k))*CH + cc + c];
        }
        __syncthreads();
        float acc[32];
        #pragma unroll
        for (int i = 0; i < 32; i++) acc[i] = 0.f;
        #pragma unroll
        for (int yy = 0; yy < 32; yy++) {
            float v = slab[yy][t];
            const float4* gp = (const float4*)&ghB[yy*32];
            #pragma unroll
            for (int q = 0; q < 8; q++) {
                float4 g4 = gp[q];
                acc[q*4+0] += g4.x*v; acc[q*4+1] += g4.y*v;
                acc[q*4+2] += g4.z*v; acc[q*4+3] += g4.w*v;
            }
        }
        // p = i*32+k  ->  viewed row = i*16 + (k>>1), col = (k&1)*512 + c
        #pragma unroll
        for (int i = 0; i < 32; i++)
            g_act[((size_t)(b*1024 + i*16 + kr))*1024 + half*512 + cc + t] = acc[i];
    }
}

// ---------------- 3x3 patch self-attention (per-pixel block) --------------
__global__ void k_attn() {
    int xq = blockIdx.x, yq = blockIdx.y, b = blockIdx.z, t = threadIdx.x; // 256
    int p = yq*32 + xq;
    size_t base = (size_t)b*HW;
    __shared__ float part[9][8];
    __shared__ float attn[9];
    int pn[9]; bool valid[9];
    #pragma unroll
    for (int kk = 0; kk < 9; kk++) {
        int dy = kk/3 - 1, dx = kk%3 - 1;
        int yy = yq + dy, xx = xq + dx;
        valid[kk] = (yy >= 0 && yy < 32 && xx >= 0 && xx < 32);
        pn[kk] = yy*32 + xx;
    }
    float sc0 = g_sigT[(base + p)*CH + t];
    float sc1 = g_sigT[(base + p)*CH + t + 256];
    float acc[9];
    #pragma unroll
    for (int kk = 0; kk < 9; kk++) {
        if (valid[kk]) {
            const float* q = &g_sigT[(base + pn[kk])*CH];
            acc[kk] = sc0*q[t] + sc1*q[t+256];
        } else acc[kk] = 0.f;           // zero-padded patch -> logit 0
    }
    #pragma unroll
    for (int kk = 0; kk < 9; kk++)
        #pragma unroll
        for (int o = 16; o; o >>= 1) acc[kk] += __shfl_xor_sync(~0u, acc[kk], o);
    if ((t & 31) == 0) {
        #pragma unroll
        for (int kk = 0; kk < 9; kk++) part[kk][t >> 5] = acc[kk];
    }
    __syncthreads();
    if (t == 0) {
        float lg[9], m = -1e30f;
        #pragma unroll
        for (int kk = 0; kk < 9; kk++) {
            float s = 0.f;
            #pragma unroll
            for (int w = 0; w < 8; w++) s += part[kk][w];
            lg[kk] = s * (1.0f/CH);
            m = fmaxf(m, lg[kk]);
        }
        float den = 0.f, e[9];
        #pragma unroll
        for (int kk = 0; kk < 9; kk++) { e[kk] = __expf(lg[kk]-m); den += e[kk]; }
        float rd = 1.f/den;
        #pragma unroll
        for (int kk = 0; kk < 9; kk++) attn[kk] = e[kk]*rd;
    }
    __syncthreads();
    float aw[9];
    #pragma unroll
    for (int kk = 0; kk < 9; kk++) aw[kk] = attn[kk];
    size_t obase = ((size_t)(b*1024 + 512 + (p >> 1)))*1024 + (p & 1)*512;
    for (int c = t; c < CH; c += 256) {
        float g = 0.f;
        #pragma unroll
        for (int kk = 0; kk < 9; kk++)
            if (valid[kk]) g += aw[kk]*g_fT[(base + pn[kk])*CH + c];
        g_act[obase + c] = g;
    }
}

// ---------------- down 1x1 conv: z[b] = W[512x1024] @ act[b][1024x1024] ----
__global__ void __launch_bounds__(256) k_down(const float* __restrict__ Wd) {
    int b = blockIdx.z;
    int m0 = blockIdx.y*128, n0 = blockIdx.x*128;
    const float* Bm = g_act + (size_t)b*1024*1024;
    float* Cm = g_z + (size_t)b*CH*HW;
    __shared__ float As[8][128];
    __shared__ float Bs[8][128];
    int t = threadIdx.x;
    int tm = t >> 4, tn = t & 15;
    float acc[8][8];
    #pragma unroll
    for (int i = 0; i < 8; i++)
        #pragma unroll
        for (int j = 0; j < 8; j++) acc[i][j] = 0.f;
    int arow = t >> 1, acol = (t & 1)*4;
    int brow = t >> 5, bcol = (t & 31)*4;
    for (int k0 = 0; k0 < 1024; k0 += 8) {
        float4 va = *(const float4*)&Wd[(size_t)(m0+arow)*1024 + k0 + acol];
        float4 vb = *(const float4*)&Bm[(size_t)(k0+brow)*1024 + n0 + bcol];
        As[acol+0][arow] = va.x; As[acol+1][arow] = va.y;
        As[acol+2][arow] = va.z; As[acol+3][arow] = va.w;
        *(float4*)&Bs[brow][bcol] = vb;
        __syncthreads();
        #pragma unroll
        for (int kk = 0; kk < 8; kk++) {
            float a[8], bb[8];
            *(float4*)(a)   = *(const float4*)&As[kk][tm*8];
            *(float4*)(a+4) = *(const float4*)&As[kk][tm*8+4];
            *(float4*)(bb)   = *(const float4*)&Bs[kk][tn*8];
            *(float4*)(bb+4) = *(const float4*)&Bs[kk][tn*8+4];
            #pragma unroll
            for (int i = 0; i < 8; i++)
                #pragma unroll
                for (int j = 0; j < 8; j++) acc[i][j] += a[i]*bb[j];
        }
        __syncthreads();
    }
    #pragma unroll
    for (int i = 0; i < 8; i++) {
        float4 v0 = make_float4(acc[i][0], acc[i][1], acc[i][2], acc[i][3]);
        float4 v1 = make_float4(acc[i][4], acc[i][5], acc[i][6], acc[i][7]);
        size_t r = (size_t)(m0 + tm*8 + i)*1024 + n0 + tn*8;
        *(float4*)&Cm[r]   = v0;
        *(float4*)&Cm[r+4] = v1;
    }
}

// ---------------- fused InstanceNorm + LeakyReLU --------------------------
__global__ void k_finish(float* __restrict__ out) {
    int o = blockIdx.x, b = blockIdx.y, t = threadIdx.x; // 256
    size_t base = (size_t)(b*CH + o)*HW;
    float v[4]; float s = 0.f, sq = 0.f;
    #pragma unroll
    for (int j = 0; j < 4; j++) {
        v[j] = g_z[base + t + j*256];
        s += v[j]; sq += v[j]*v[j];
    }
    #pragma unroll
    for (int o2 = 16; o2; o2 >>= 1) {
        s  += __shfl_xor_sync(~0u, s,  o2);
        sq += __shfl_xor_sync(~0u, sq, o2);
    }
    __shared__ float ws[8][2];
    __shared__ float smu, srs;
    if ((t & 31) == 0) { ws[t>>5][0] = s; ws[t>>5][1] = sq; }
    __syncthreads();
    if (t == 0) {
        float S = 0.f, Q = 0.f;
        #pragma unroll
        for (int w = 0; w < 8; w++) { S += ws[w][0]; Q += ws[w][1]; }
        float mu = S*(1.0f/HW);
        float var = Q*(1.0f/HW) - mu*mu;
        smu = mu; srs = rsqrtf(var + 1e-5f);
    }
    __syncthreads();
    #pragma unroll
    for (int j = 0; j < 4; j++) {
        float zn = (v[j] - smu)*srs;
        out[base + t + j*256] = zn >= 0.f ? zn : 0.2f*zn;
    }
}

// ---------------- launch ---------------------------------------------------
extern "C" void kernel_launch(void* const* d_in, const int* in_sizes, int n_in,
                              void* d_out, int out_size) {
    const float* x   = (const float*)d_in[0];
    const float* w1  = (const float*)d_in[1];
    const float* b1  = (const float*)d_in[2];
    const float* w2  = (const float*)d_in[3];
    const float* b2  = (const float*)d_in[4];
    const float* dw  = (const float*)d_in[5];
    const float* gus = (const float*)d_in[6];
    float* out = (float*)d_out;

    k_ghat<<<1, 1024>>>(gus);
    k_se_reduce<<<dim3(CH, NB), 128>>>(x);
    k_se_mlp<<<NB, 512>>>(w1, b1, w2, b2);
    k_makeT<<<dim3(32, 16, NB), dim3(32, 8)>>>(x);
    k_gusA<<<dim3(32, NB), 256>>>();
    k_gusB<<<dim3(32, NB), 256>>>();
    k_attn<<<dim3(32, 32, NB), 256>>>();
    k_down<<<dim3(8, 4, NB), 256>>>(dw);
    k_finish<<<dim3(CH, NB), 256>>>(out);
}

// round 3
// speedup vs baseline: 1.4970x; 1.4970x over previous
#include <cuda_runtime.h>
#include <cuda_bf16.h>
#include <math.h>
#include <stdint.h>

#define NB 16
#define CH 512
#define HW 1024

// ---------------- scratch (static device globals) --------------------------
__device__ float g_ghat[32*32];
__device__ float g_s[NB*CH];
__device__ float g_ysc[NB*CH];
__device__ float g_fT[(size_t)NB*HW*CH];
__device__ float g_sigT[(size_t)NB*HW*CH];
__device__ float g_w1buf[(size_t)NB*32*32*CH];
__device__ float g_act[(size_t)NB*1024*1024];    // cat in viewed layout [b][i][p]
__device__ float g_z[(size_t)NB*CH*HW];
__device__ __nv_bfloat16 g_A[(size_t)512*3072];          // [Ah | Al | Ah]
__device__ __nv_bfloat16 g_BT[(size_t)NB*1024*2048];     // [b][p][ hi(1024) | lo(1024) ]

// ---------------- PTX helpers ----------------------------------------------
__device__ __forceinline__ uint32_t smem_u32(const void* p) {
    uint32_t a;
    asm("{ .reg .u64 t; cvta.to.shared.u64 t, %1; cvt.u32.u64 %0, t; }" : "=r"(a) : "l"(p));
    return a;
}
__device__ __forceinline__ void cpasync16(uint32_t saddr, const void* gaddr) {
    asm volatile("cp.async.cg.shared.global [%0], [%1], 16;" :: "r"(saddr), "l"(gaddr) : "memory");
}
__device__ __forceinline__ void cp_commit() { asm volatile("cp.async.commit_group;" ::: "memory"); }
__device__ __forceinline__ void cp_wait1() { asm volatile("cp.async.wait_group 1;" ::: "memory"); }
__device__ __forceinline__ void cp_wait0() { asm volatile("cp.async.wait_group 0;" ::: "memory"); }
__device__ __forceinline__ uint32_t swz(uint32_t x) { return x ^ ((x >> 3) & 0x70); }

// ---------------- ghat extraction -----------------------------------------
__global__ void k_ghat(const float* __restrict__ gus) {
    int t = threadIdx.x;
    int i = t >> 5, y = t & 31;
    const float* p = gus + (size_t)(i*32)*1024 + y*32;
    float s = 0.f;
    #pragma unroll
    for (int x = 0; x < 32; x++) s += p[x];
    g_ghat[t] = s;
}

// ---------------- SE: spatial mean -----------------------------------------
__global__ void k_se_reduce(const float* __restrict__ x) {
    int c = blockIdx.x, b = blockIdx.y, t = threadIdx.x;
    const float* p = x + ((size_t)(b*CH + c))*HW;
    float s = 0.f;
    #pragma unroll
    for (int j = 0; j < 8; j++) s += p[t + j*128];
    #pragma unroll
    for (int o = 16; o; o >>= 1) s += __shfl_xor_sync(~0u, s, o);
    __shared__ float ws[4];
    if ((t & 31) == 0) ws[t >> 5] = s;
    __syncthreads();
    if (t == 0) g_s[b*CH + c] = (ws[0]+ws[1]+ws[2]+ws[3]) * (1.0f/HW);
}

// ---------------- SE: tiny MLP ---------------------------------------------
__global__ void k_se_mlp(const float* __restrict__ w1, const float* __restrict__ b1,
                         const float* __restrict__ w2, const float* __restrict__ b2) {
    int b = blockIdx.x, t = threadIdx.x;
    __shared__ float ssh[CH];
    __shared__ float hsh[32];
    ssh[t] = g_s[b*CH + t];
    __syncthreads();
    if (t < 32) {
        float a = b1[t];
        const float* w = w1 + t*CH;
        for (int c = 0; c < CH; c++) a += w[c]*ssh[c];
        hsh[t] = fmaxf(a, 0.f);
    }
    __syncthreads();
    float a = b2[t];
    const float* w = w2 + t*32;
    #pragma unroll
    for (int j = 0; j < 32; j++) a += w[j]*hsh[j];
    g_ysc[b*CH + t] = 1.f/(1.f + __expf(-a));
}

// ---------------- out32 transpose + sigmoid --------------------------------
__global__ void k_makeT(const float* __restrict__ x) {
    int p0 = blockIdx.x*32, c0 = blockIdx.y*32, b = blockIdx.z;
    int tx = threadIdx.x, ty = threadIdx.y;
    __shared__ float tile[32][33];
    #pragma unroll
    for (int i = 0; i < 4; i++) {
        int c = c0 + ty + i*8;
        tile[ty+i*8][tx] = x[((size_t)(b*CH + c))*HW + p0 + tx] * g_ysc[b*CH + c];
    }
    __syncthreads();
    #pragma unroll
    for (int i = 0; i < 4; i++) {
        int p = p0 + ty + i*8;
        float v = tile[tx][ty+i*8];
        size_t idx = ((size_t)(b*HW + p))*CH + c0 + tx;
        g_fT[idx] = v;
        g_sigT[idx] = 1.f/(1.f + __expf(-v));
    }
}

// ---------------- gus stage A ----------------------------------------------
__global__ void k_gusA() {
    int y = blockIdx.x, b = blockIdx.y, t = threadIdx.x;
    __shared__ float ghT[1024];
    __shared__ float slab[32][256];
    for (int idx = t; idx < 1024; idx += 256) {
        int xx = idx >> 5, k = idx & 31;
        ghT[idx] = g_ghat[k*32 + xx];
    }
    for (int cc = 0; cc < CH; cc += 256) {
        __syncthreads();
        for (int idx = t; idx < 32*256; idx += 256) {
            int xr = idx >> 8, c = idx & 255;
            slab[xr][c] = g_fT[((size_t)(b*HW + y*32 + xr))*CH + cc + c];
        }
        __syncthreads();
        float acc[32];
        #pragma unroll
        for (int k = 0; k < 32; k++) acc[k] = 0.f;
        #pragma unroll
        for (int xx = 0; xx < 32; xx++) {
            float v = slab[xx][t];
            const float4* gp = (const float4*)&ghT[xx*32];
            #pragma unroll
            for (int q = 0; q < 8; q++) {
                float4 g4 = gp[q];
                acc[q*4+0] += g4.x*v; acc[q*4+1] += g4.y*v;
                acc[q*4+2] += g4.z*v; acc[q*4+3] += g4.w*v;
            }
        }
        #pragma unroll
        for (int k = 0; k < 32; k++)
            g_w1buf[((size_t)((b*32 + y)*32 + k))*CH + cc + t] = acc[k];
    }
}

// ---------------- gus stage B ----------------------------------------------
__global__ void k_gusB() {
    int k = blockIdx.x, b = blockIdx.y, t = threadIdx.x;
    __shared__ float ghB[1024];
    __shared__ float slab[32][256];
    for (int idx = t; idx < 1024; idx += 256) {
        int yy = idx >> 5, i = idx & 31;
        ghB[idx] = g_ghat[i*32 + yy];
    }
    int half = k & 1, kr = k >> 1;
    for (int cc = 0; cc < CH; cc += 256) {
        __syncthreads();
        for (int idx = t; idx < 32*256; idx += 256) {
            int yr = idx >> 8, c = idx & 255;
            slab[yr][c] = g_w1buf[((size_t)((b*32 + yr)*32 + k))*CH + cc + c];
        }
        __syncthreads();
        float acc[32];
        #pragma unroll
        for (int i = 0; i < 32; i++) acc[i] = 0.f;
        #pragma unroll
        for (int yy = 0; yy < 32; yy++) {
            float v = slab[yy][t];
            const float4* gp = (const float4*)&ghB[yy*32];
            #pragma unroll
            for (int q = 0; q < 8; q++) {
                float4 g4 = gp[q];
                acc[q*4+0] += g4.x*v; acc[q*4+1] += g4.y*v;
                acc[q*4+2] += g4.z*v; acc[q*4+3] += g4.w*v;
            }
        }
        #pragma unroll
        for (int i = 0; i < 32; i++)
            g_act[((size_t)(b*1024 + i*16 + kr))*1024 + half*512 + cc + t] = acc[i];
    }
}

// ---------------- 3x3 patch self-attention ---------------------------------
__global__ void k_attn() {
    int xq = blockIdx.x, yq = blockIdx.y, b = blockIdx.z, t = threadIdx.x;
    int p = yq*32 + xq;
    size_t base = (size_t)b*HW;
    __shared__ float part[9][8];
    __shared__ float attn[9];
    int pn[9]; bool valid[9];
    #pragma unroll
    for (int kk = 0; kk < 9; kk++) {
        int dy = kk/3 - 1, dx = kk%3 - 1;
        int yy = yq + dy, xx = xq + dx;
        valid[kk] = (yy >= 0 && yy < 32 && xx >= 0 && xx < 32);
        pn[kk] = yy*32 + xx;
    }
    float sc0 = g_sigT[(base + p)*CH + t];
    float sc1 = g_sigT[(base + p)*CH + t + 256];
    float acc[9];
    #pragma unroll
    for (int kk = 0; kk < 9; kk++) {
        if (valid[kk]) {
            const float* q = &g_sigT[(base + pn[kk])*CH];
            acc[kk] = sc0*q[t] + sc1*q[t+256];
        } else acc[kk] = 0.f;
    }
    #pragma unroll
    for (int kk = 0; kk < 9; kk++)
        #pragma unroll
        for (int o = 16; o; o >>= 1) acc[kk] += __shfl_xor_sync(~0u, acc[kk], o);
    if ((t & 31) == 0) {
        #pragma unroll
        for (int kk = 0; kk < 9; kk++) part[kk][t >> 5] = acc[kk];
    }
    __syncthreads();
    if (t == 0) {
        float lg[9], m = -1e30f;
        #pragma unroll
        for (int kk = 0; kk < 9; kk++) {
            float s = 0.f;
            #pragma unroll
            for (int w = 0; w < 8; w++) s += part[kk][w];
            lg[kk] = s * (1.0f/CH);
            m = fmaxf(m, lg[kk]);
        }
        float den = 0.f, e[9];
        #pragma unroll
        for (int kk = 0; kk < 9; kk++) { e[kk] = __expf(lg[kk]-m); den += e[kk]; }
        float rd = 1.f/den;
        #pragma unroll
        for (int kk = 0; kk < 9; kk++) attn[kk] = e[kk]*rd;
    }
    __syncthreads();
    float aw[9];
    #pragma unroll
    for (int kk = 0; kk < 9; kk++) aw[kk] = attn[kk];
    size_t obase = ((size_t)(b*1024 + 512 + (p >> 1)))*1024 + (p & 1)*512;
    for (int c = t; c < CH; c += 256) {
        float g = 0.f;
        #pragma unroll
        for (int kk = 0; kk < 9; kk++)
            if (valid[kk]) g += aw[kk]*g_fT[(base + pn[kk])*CH + c];
        g_act[obase + c] = g;
    }
}

// ---------------- A convert: Wd -> bf16 split [Ah|Al|Ah] -------------------
__global__ void k_convA(const float* __restrict__ Wd) {
    int r = blockIdx.x, c = threadIdx.x;  // <<<512, 1024>>>
    float w = Wd[(size_t)r*1024 + c];
    __nv_bfloat16 hi = __float2bfloat16(w);
    __nv_bfloat16 lo = __float2bfloat16(w - __bfloat162float(hi));
    size_t base = (size_t)r*3072;
    g_A[base + c] = hi;
    g_A[base + 1024 + c] = lo;
    g_A[base + 2048 + c] = hi;
}

// ---------------- act transpose + bf16 split -------------------------------
__global__ void k_actT() {
    int p0 = blockIdx.x*32, i0 = blockIdx.y*32, b = blockIdx.z;
    int tx = threadIdx.x, ty = threadIdx.y;   // (32,8)
    __shared__ float tile[32][33];
    #pragma unroll
    for (int j = 0; j < 4; j++) {
        int i = i0 + ty + j*8;
        tile[ty+j*8][tx] = g_act[((size_t)(b*1024 + i))*1024 + p0 + tx];
    }
    __syncthreads();
    #pragma unroll
    for (int j = 0; j < 4; j++) {
        int p = p0 + ty + j*8;
        float v = tile[tx][ty+j*8];
        __nv_bfloat16 hi = __float2bfloat16(v);
        __nv_bfloat16 lo = __float2bfloat16(v - __bfloat162float(hi));
        size_t rb = ((size_t)(b*1024 + p))*2048;
        g_BT[rb + i0 + tx] = hi;
        g_BT[rb + 1024 + i0 + tx] = lo;
    }
}

// ---------------- down GEMM via mma.sync bf16 (HMMA) -----------------------
// C[b] (512x1024) = A'(512x3072) @ B'(3072x1024),  A' = [Ah|Al|Ah]
// B' block rows: [0,1024)->BT hi, [1024,2048)->BT hi, [2048,3072)->BT lo
__global__ void __launch_bounds__(256, 1) k_down_mma() {
    __shared__ __nv_bfloat16 As[3][128*32];
    __shared__ __nv_bfloat16 Bs[3][128*32];
    int t = threadIdx.x, lane = t & 31, wid = t >> 5;
    int m0 = blockIdx.x*128, n0 = blockIdx.y*128, b = blockIdx.z;
    int wm = (wid & 3)*32, wn = (wid >> 2)*64;

    const __nv_bfloat16* Bb = g_BT + (size_t)b*1024*2048;

    float acc[2][8][4];
    #pragma unroll
    for (int i = 0; i < 2; i++)
        #pragma unroll
        for (int j = 0; j < 8; j++)
            #pragma unroll
            for (int r = 0; r < 4; r++) acc[i][j][r] = 0.f;

    auto load_stage = [&](int kb, int s) {
        int kp = kb*32;
        int bcol = kp < 2048 ? (kp & 1023) : (kp - 1024);
        uint32_t sa = smem_u32(&As[s][0]);
        uint32_t sbm = smem_u32(&Bs[s][0]);
        #pragma unroll
        for (int i = 0; i < 2; i++) {
            int ch = t + i*256;
            int row = ch >> 2, c = ch & 3;
            cpasync16(sa + swz(row*64 + c*16),
                      g_A + ((size_t)(m0+row)*3072 + kp + c*8));
            cpasync16(sbm + swz(row*64 + c*16),
                      Bb + ((size_t)(n0+row)*2048 + bcol + c*8));
        }
        cp_commit();
    };

    load_stage(0, 0);
    load_stage(1, 1);

    for (int kb = 0; kb < 96; kb++) {
        int s = kb - (kb/3)*3;
        if (kb < 95) cp_wait1(); else cp_wait0();
        __syncthreads();
        if (kb + 2 < 96) load_stage(kb+2, (kb+2) - ((kb+2)/3)*3);

        uint32_t abase = smem_u32(&As[s][0]);
        uint32_t bbase = smem_u32(&Bs[s][0]);
        int tl = lane >> 3, rw = lane & 7;
        #pragma unroll
        for (int k16 = 0; k16 < 2; k16++) {
            int k0 = k16*16;
            uint32_t af[2][4];
            #pragma unroll
            for (int i = 0; i < 2; i++) {
                int mm = wm + i*16 + (tl & 1)*8 + rw;
                int kk = k0 + (tl >> 1)*8;
                uint32_t ad = abase + swz((uint32_t)(mm*64 + kk*2));
                asm volatile("ldmatrix.sync.aligned.m8n8.x4.shared.b16 {%0,%1,%2,%3}, [%4];"
                             : "=r"(af[i][0]), "=r"(af[i][1]), "=r"(af[i][2]), "=r"(af[i][3])
                             : "r"(ad));
            }
            uint32_t bfr[4][4];
            #pragma unroll
            for (int j2 = 0; j2 < 4; j2++) {
                int nn = wn + j2*16 + (tl >> 1)*8 + rw;
                int kk = k0 + (tl & 1)*8;
                uint32_t bd = bbase + swz((uint32_t)(nn*64 + kk*2));
                asm volatile("ldmatrix.sync.aligned.m8n8.x4.shared.b16 {%0,%1,%2,%3}, [%4];"
                             : "=r"(bfr[j2][0]), "=r"(bfr[j2][1]), "=r"(bfr[j2][2]), "=r"(bfr[j2][3])
                             : "r"(bd));
            }
            #pragma unroll
            for (int i = 0; i < 2; i++)
                #pragma unroll
                for (int j = 0; j < 8; j++) {
                    uint32_t b0 = bfr[j >> 1][(j & 1)*2 + 0];
                    uint32_t b1 = bfr[j >> 1][(j & 1)*2 + 1];
                    asm volatile(
                        "mma.sync.aligned.m16n8k16.row.col.f32.bf16.bf16.f32 "
                        "{%0,%1,%2,%3}, {%4,%5,%6,%7}, {%8,%9}, {%0,%1,%2,%3};"
                        : "+f"(acc[i][j][0]), "+f"(acc[i][j][1]),
                          "+f"(acc[i][j][2]), "+f"(acc[i][j][3])
                        : "r"(af[i][0]), "r"(af[i][1]), "r"(af[i][2]), "r"(af[i][3]),
                          "r"(b0), "r"(b1));
                }
        }
    }

    // epilogue: write g_z
    float* Cm = g_z + (size_t)b*512*1024;
    #pragma unroll
    for (int i = 0; i < 2; i++) {
        int mrow = m0 + wm + i*16 + (lane >> 2);
        #pragma unroll
        for (int j = 0; j < 8; j++) {
            int n = n0 + wn + j*8 + (lane & 3)*2;
            *(float2*)&Cm[(size_t)mrow*1024 + n]       = make_float2(acc[i][j][0], acc[i][j][1]);
            *(float2*)&Cm[(size_t)(mrow+8)*1024 + n]   = make_float2(acc[i][j][2], acc[i][j][3]);
        }
    }
}

// ---------------- fused InstanceNorm + LeakyReLU ---------------------------
__global__ void k_finish(float* __restrict__ out) {
    int o = blockIdx.x, b = blockIdx.y, t = threadIdx.x;
    size_t base = (size_t)(b*CH + o)*HW;
    float v[4]; float s = 0.f, sq = 0.f;
    #pragma unroll
    for (int j = 0; j < 4; j++) {
        v[j] = g_z[base + t + j*256];
        s += v[j]; sq += v[j]*v[j];
    }
    #pragma unroll
    for (int o2 = 16; o2; o2 >>= 1) {
        s  += __shfl_xor_sync(~0u, s,  o2);
        sq += __shfl_xor_sync(~0u, sq, o2);
    }
    __shared__ float ws[8][2];
    __shared__ float smu, srs;
    if ((t & 31) == 0) { ws[t>>5][0] = s; ws[t>>5][1] = sq; }
    __syncthreads();
    if (t == 0) {
        float S = 0.f, Q = 0.f;
        #pragma unroll
        for (int w = 0; w < 8; w++) { S += ws[w][0]; Q += ws[w][1]; }
        float mu = S*(1.0f/HW);
        float var = Q*(1.0f/HW) - mu*mu;
        smu = mu; srs = rsqrtf(var + 1e-5f);
    }
    __syncthreads();
    #pragma unroll
    for (int j = 0; j < 4; j++) {
        float zn = (v[j] - smu)*srs;
        out[base + t + j*256] = zn >= 0.f ? zn : 0.2f*zn;
    }
}

// ---------------- launch ----------------------------------------------------
extern "C" void kernel_launch(void* const* d_in, const int* in_sizes, int n_in,
                              void* d_out, int out_size) {
    const float* x   = (const float*)d_in[0];
    const float* w1  = (const float*)d_in[1];
    const float* b1  = (const float*)d_in[2];
    const float* w2  = (const float*)d_in[3];
    const float* b2  = (const float*)d_in[4];
    const float* dw  = (const float*)d_in[5];
    const float* gus = (const float*)d_in[6];
    float* out = (float*)d_out;

    k_ghat<<<1, 1024>>>(gus);
    k_se_reduce<<<dim3(CH, NB), 128>>>(x);
    k_se_mlp<<<NB, 512>>>(w1, b1, w2, b2);
    k_makeT<<<dim3(32, 16, NB), dim3(32, 8)>>>(x);
    k_convA<<<512, 1024>>>(dw);
    k_gusA<<<dim3(32, NB), 256>>>();
    k_gusB<<<dim3(32, NB), 256>>>();
    k_attn<<<dim3(32, 32, NB), 256>>>();
    k_actT<<<dim3(32, 32, NB), dim3(32, 8)>>>();
    k_down_mma<<<dim3(4, 8, NB), 256>>>();
    k_finish<<<dim3(CH, NB), 256>>>(out);
}